// round 1
// baseline (speedup 1.0000x reference)
#include <cuda_runtime.h>
#include <cuda_bf16.h>

// ShoeboxToRIR: image-source RIR, B=256 rooms, 1561 images (|g|_1 <= 10),
// 81-tap windowed sinc per image scattered into rir[8000], plus toa[256].
//
// Key optimizations vs reference math:
//  - all 6 walls share one absorption -> att = tr^(|gx|+|gy|+|gz|)
//  - sin(pi*(n+frac)) = (-1)^n * sin(pi*frac): one sinpif per image
//  - race-free shared-mem scatter: thread t owns samples == t (mod 128);
//    window width 81 < 128 so each thread has at most one tap per image.

#define NIMG     1561
#define NBATCH   256
#define RIRLEN   8000
#define NTHREADS 128
#define FILTLEN  81
#define PADK     40

__global__ __launch_bounds__(NTHREADS, 4)
void shoebox_rir_kernel(const float* __restrict__ in,
                        float* __restrict__ out,
                        int write_toa)
{
    extern __shared__ float smem[];
    float*  rir_s  = smem;                         // RIRLEN floats
    float4* params = (float4*)(smem + RIRLEN);     // NIMG float4

    const int b = blockIdx.x;
    const int t = threadIdx.x;

    const float* ip = in + b * 10;
    const float rx = ip[0], ry = ip[1], rz = ip[2];
    const float mx = ip[3] * rx, my = ip[4] * ry, mz = ip[5] * rz;
    const float sx = ip[6] * rx, sy = ip[7] * ry, sz = ip[8] * rz;
    const float ab = ip[9];
    const float tr = sqrtf(1.0f - ab);

    // zero the shared RIR accumulator
    for (int p = t; p < RIRLEN; p += NTHREADS) rir_s[p] = 0.0f;

    // ---- phase 1: per-image parameters ----
    for (int slot = t; slot < NIMG; slot += NTHREADS) {
        // decode slot -> (gx, gy, gz) over {g : |gx|+|gy|+|gz| <= 10}
        int s = slot;
        int gx = 0, gy = 0, gz = 0;
        #pragma unroll 1
        for (int x = -10; x <= 10; ++x) {
            int r = 10 - abs(x);
            int c = 2 * r * r + 2 * r + 1;     // count of (gy,gz) with |gy|+|gz|<=r
            if (s < c) { gx = x; break; }
            s -= c;
        }
        const int rr = 10 - abs(gx);
        #pragma unroll 1
        for (int y = -rr; y <= rr; ++y) {
            int c = 2 * (rr - abs(y)) + 1;
            if (s < c) { gy = y; break; }
            s -= c;
        }
        gz = -(rr - abs(gy)) + s;

        // image position (odd coord: room*(g+1) - src ; even: room*g + src)
        const float ix = (gx & 1) ? (rx * (float)(gx + 1) - sx) : (rx * (float)gx + sx);
        const float iy = (gy & 1) ? (ry * (float)(gy + 1) - sy) : (ry * (float)gy + sy);
        const float iz = (gz & 1) ? (rz * (float)(gz + 1) - sz) : (rz * (float)gz + sz);

        const float dx = ix - mx, dy = iy - my, dz = iz - mz;
        const float dist = sqrtf(dx * dx + dy * dy + dz * dz);

        // attenuation: tr^(|gx|+|gy|+|gz|)
        int E = abs(gx) + abs(gy) + abs(gz);
        float att = 1.0f;
        #pragma unroll 1
        for (int e = 0; e < E; ++e) att *= tr;

        const float amp    = att / dist;
        const float delay  = dist * 16000.0f / 343.0f;
        const float di     = ceilf(delay);
        const float frac   = di - delay;               // in [0,1)
        const int   astart = (int)di - PADK;           // first sample of window
        const float sp     = sinpif(frac);             // sin(pi*frac)

        params[slot] = make_float4(amp, sp, frac, __int_as_float(astart));
    }

    if (t == 0 && write_toa) {
        const float ddx = mx - sx, ddy = my - sy, ddz = mz - sz;
        const float d = sqrtf(ddx * ddx + ddy * ddy + ddz * ddz);
        out[NBATCH * RIRLEN + b] = 40.0f + d * 16000.0f / 343.0f;
    }

    __syncthreads();

    // ---- phase 2: accumulate taps; thread t owns samples == t (mod 128) ----
    const float PI_F     = 3.14159265358979323846f;
    const float PI_OV_40 = 0.07853981633974483f;

    #pragma unroll 1
    for (int i = 0; i < NIMG; ++i) {
        const float4 p = params[i];
        const int a = __float_as_int(p.w);
        if (a >= RIRLEN) continue;                 // whole window beyond rir (uniform skip)

        const int j = (t - a) & (NTHREADS - 1);    // tap index owned by this thread
        if (j < FILTLEN) {
            const int pos = a + j;                  // == t (mod 128) by construction
            if ((unsigned)pos < (unsigned)RIRLEN) {
                const float x = (float)(j - PADK) + p.z;
                // hann window: 0.5*(1 + cos(pi*x/40)), zero for |x| > 40
                float hv = 0.5f + 0.5f * __cosf(x * PI_OV_40);
                if (fabsf(x) > 40.0f) hv = 0.0f;
                // sinc: (-1)^(j-40) * sin(pi*frac) / (pi*x);  sinc(0) = 1
                const float sgn = (j & 1) ? -p.y : p.y;
                const float sincv = (x == 0.0f) ? 1.0f : __fdividef(sgn, PI_F * x);
                rir_s[pos] += p.x * sincv * hv;
            }
        }
    }

    __syncthreads();

    // ---- phase 3: write RIR (coalesced) ----
    float* orow = out + (size_t)b * RIRLEN;
    for (int p = t; p < RIRLEN; p += NTHREADS) orow[p] = rir_s[p];
}

extern "C" void kernel_launch(void* const* d_in, const int* in_sizes, int n_in,
                              void* d_out, int out_size)
{
    const float* in  = (const float*)d_in[0];
    float*       out = (float*)d_out;

    const int smem_bytes = RIRLEN * sizeof(float) + NIMG * sizeof(float4); // 56976
    cudaFuncSetAttribute(shoebox_rir_kernel,
                         cudaFuncAttributeMaxDynamicSharedMemorySize, smem_bytes);

    const int write_toa = (out_size >= NBATCH * RIRLEN + NBATCH) ? 1 : 0;
    shoebox_rir_kernel<<<NBATCH, NTHREADS, smem_bytes>>>(in, out, write_toa);
}

// round 4
// speedup vs baseline: 1.7154x; 1.7154x over previous
#include <cuda_runtime.h>
#include <cuda_bf16.h>

// ShoeboxToRIR: image-source RIR, B=256 rooms, 1561 images (|g|_1 <= 10),
// 81-tap windowed sinc per image scattered into rir[8000], plus toa[256].
//
// Structure:
//  - decode_kernel: one-shot packed table slot -> (gx,gy,gz,E)
//  - main kernel: 256 CTAs x 512 threads. 4 sub-blocks of 128 threads, each
//    with a PRIVATE smem RIR copy, each processing 1/4 of the images.
//    Thread t of a sub-block owns samples == t (mod 128) of its copy
//    (window width 81 < 128 -> at most one tap per image per thread,
//    race-free, deterministic). Final in-block 4-way reduction.
//  - fallback single-copy 128-thread kernel if the big smem opt-in fails.

#define NIMG     1561
#define NBATCH   256
#define RIRLEN   8000
#define NSUB     4
#define SUBTH    128
#define NTH      (NSUB * SUBTH)
#define CHUNK    ((NIMG + NSUB - 1) / NSUB)   // 391
#define FILTLEN  81
#define PADK     40

__device__ int g_table[NIMG];   // packed: (gx+10) | (gy+10)<<5 | (gz+10)<<10 | E<<15

__global__ void decode_kernel()
{
    int slot = blockIdx.x * blockDim.x + threadIdx.x;
    if (slot >= NIMG) return;
    int s = slot;
    int gx = 0, gy = 0, gz = 0;
    #pragma unroll 1
    for (int x = -10; x <= 10; ++x) {
        int r = 10 - abs(x);
        int c = 2 * r * r + 2 * r + 1;
        if (s < c) { gx = x; break; }
        s -= c;
    }
    const int rr = 10 - abs(gx);
    #pragma unroll 1
    for (int y = -rr; y <= rr; ++y) {
        int c = 2 * (rr - abs(y)) + 1;
        if (s < c) { gy = y; break; }
        s -= c;
    }
    gz = -(rr - abs(gy)) + s;
    int E = abs(gx) + abs(gy) + abs(gz);
    g_table[slot] = (gx + 10) | ((gy + 10) << 5) | ((gz + 10) << 10) | (E << 15);
}

__device__ __forceinline__ void tap_add(float4 p, int t, float* __restrict__ myrir)
{
    const float PI_OV_40 = 0.07853981633974483f;
    const int a = __float_as_int(p.w);
    const int j = (t - a) & (SUBTH - 1);       // tap index owned by this thread
    if (j < FILTLEN) {
        const int pos = a + j;                  // == t (mod 128) by construction
        if ((unsigned)pos < (unsigned)RIRLEN) {
            const float x = (float)(j - PADK) + p.z;
            float hv = 0.5f + 0.5f * __cosf(x * PI_OV_40);
            if (fabsf(x) > 40.0f) hv = 0.0f;    // only possible at j==80
            float v;
            if (x == 0.0f) {
                v = p.x;                        // sinc(0)=1, hann(0)=1 -> amp
            } else {
                const float q = (j & 1) ? -p.y : p.y;   // p.y = amp*sin(pi*frac)/pi
                v = __fdividef(q, x) * hv;
            }
            myrir[pos] += v;
        }
    }
}

// Shared phase-1 parameter computation.
__device__ __forceinline__ void compute_params(const float* __restrict__ ip,
                                               float4* __restrict__ params,
                                               int tid, int nth,
                                               float& mx, float& my, float& mz,
                                               float& sx, float& sy, float& sz)
{
    const float rx = ip[0], ry = ip[1], rz = ip[2];
    mx = ip[3] * rx; my = ip[4] * ry; mz = ip[5] * rz;
    sx = ip[6] * rx; sy = ip[7] * ry; sz = ip[8] * rz;
    const float tr  = sqrtf(1.0f - ip[9]);
    const float ltr = __log2f(tr);
    const float PI_F = 3.14159265358979323846f;

    for (int slot = tid; slot < NIMG; slot += nth) {
        const int pk = g_table[slot];
        const int gx = (pk & 31) - 10;
        const int gy = ((pk >> 5) & 31) - 10;
        const int gz = ((pk >> 10) & 31) - 10;
        const int E  = pk >> 15;

        const float ix = (gx & 1) ? (rx * (float)(gx + 1) - sx) : (rx * (float)gx + sx);
        const float iy = (gy & 1) ? (ry * (float)(gy + 1) - sy) : (ry * (float)gy + sy);
        const float iz = (gz & 1) ? (rz * (float)(gz + 1) - sz) : (rz * (float)gz + sz);

        const float dx = ix - mx, dy = iy - my, dz = iz - mz;
        const float dist = sqrtf(dx * dx + dy * dy + dz * dz);

        const float att   = exp2f((float)E * ltr);       // tr^E
        const float amp   = __fdividef(att, dist);
        const float delay = dist * (16000.0f / 343.0f);
        const float di    = ceilf(delay);
        const float frac  = di - delay;                  // in [0,1)
        const int   a     = (int)di - PADK;
        const float q     = amp * sinpif(frac) * (1.0f / PI_F);

        params[slot] = make_float4(amp, q, frac, __int_as_float(a));
    }
}

__global__ __launch_bounds__(NTH, 1)
void shoebox_rir_kernel(const float* __restrict__ in,
                        float* __restrict__ out,
                        int write_toa)
{
    extern __shared__ float smem[];
    float*  rir_s  = smem;                              // NSUB * RIRLEN floats
    float4* params = (float4*)(smem + NSUB * RIRLEN);   // NIMG float4

    const int b   = blockIdx.x;
    const int tid = threadIdx.x;
    const int sub = tid >> 7;
    const int t   = tid & (SUBTH - 1);

    // zero the private RIR copies
    for (int p = tid; p < NSUB * RIRLEN; p += NTH) rir_s[p] = 0.0f;

    float mx, my, mz, sx, sy, sz;
    compute_params(in + b * 10, params, tid, NTH, mx, my, mz, sx, sy, sz);

    if (tid == 0 && write_toa) {
        const float ddx = mx - sx, ddy = my - sy, ddz = mz - sz;
        const float d = sqrtf(ddx * ddx + ddy * ddy + ddz * ddz);
        out[NBATCH * RIRLEN + b] = 40.0f + d * (16000.0f / 343.0f);
    }

    __syncthreads();

    // ---- phase 2: each sub-block accumulates its image range into its copy ----
    float* myrir = rir_s + sub * RIRLEN;
    const int i0 = sub * CHUNK;
    const int i1 = (i0 + CHUNK < NIMG) ? (i0 + CHUNK) : NIMG;

    int i = i0;
    #pragma unroll 1
    for (; i + 1 < i1; i += 2) {
        const float4 p0 = params[i];
        const float4 p1 = params[i + 1];
        if (__float_as_int(p0.w) < RIRLEN) tap_add(p0, t, myrir);   // warp-uniform skip
        if (__float_as_int(p1.w) < RIRLEN) tap_add(p1, t, myrir);
    }
    if (i < i1) {
        const float4 p0 = params[i];
        if (__float_as_int(p0.w) < RIRLEN) tap_add(p0, t, myrir);
    }

    __syncthreads();

    // ---- phase 3: reduce 4 copies, write RIR (coalesced) ----
    float* orow = out + (size_t)b * RIRLEN;
    for (int p = tid; p < RIRLEN; p += NTH) {
        float v = (rir_s[p] + rir_s[RIRLEN + p])
                + (rir_s[2 * RIRLEN + p] + rir_s[3 * RIRLEN + p]);
        orow[p] = v;
    }
}

// Fallback: single-copy, 128-thread version (known-good round-1 structure).
__global__ __launch_bounds__(SUBTH, 4)
void shoebox_rir_small(const float* __restrict__ in,
                       float* __restrict__ out,
                       int write_toa)
{
    extern __shared__ float smem[];
    float*  rir_s  = smem;                         // RIRLEN floats
    float4* params = (float4*)(smem + RIRLEN);     // NIMG float4

    const int b = blockIdx.x;
    const int t = threadIdx.x;

    for (int p = t; p < RIRLEN; p += SUBTH) rir_s[p] = 0.0f;

    float mx, my, mz, sx, sy, sz;
    compute_params(in + b * 10, params, t, SUBTH, mx, my, mz, sx, sy, sz);

    if (t == 0 && write_toa) {
        const float ddx = mx - sx, ddy = my - sy, ddz = mz - sz;
        const float d = sqrtf(ddx * ddx + ddy * ddy + ddz * ddz);
        out[NBATCH * RIRLEN + b] = 40.0f + d * (16000.0f / 343.0f);
    }

    __syncthreads();

    #pragma unroll 1
    for (int i = 0; i < NIMG; ++i) {
        const float4 p = params[i];
        if (__float_as_int(p.w) < RIRLEN) tap_add(p, t, rir_s);
    }

    __syncthreads();

    float* orow = out + (size_t)b * RIRLEN;
    for (int p = t; p < RIRLEN; p += SUBTH) orow[p] = rir_s[p];
}

extern "C" void kernel_launch(void* const* d_in, const int* in_sizes, int n_in,
                              void* d_out, int out_size)
{
    const float* in  = (const float*)d_in[0];
    float*       out = (float*)d_out;

    const int big_smem   = NSUB * RIRLEN * sizeof(float) + NIMG * sizeof(float4); // 152976
    const int small_smem = RIRLEN * sizeof(float) + NIMG * sizeof(float4);        //  56976

    decode_kernel<<<(NIMG + 127) / 128, 128>>>();

    const int write_toa = (out_size >= NBATCH * RIRLEN + NBATCH) ? 1 : 0;

    cudaError_t e = cudaFuncSetAttribute(shoebox_rir_kernel,
                        cudaFuncAttributeMaxDynamicSharedMemorySize, big_smem);
    if (e == cudaSuccess) {
        shoebox_rir_kernel<<<NBATCH, NTH, big_smem>>>(in, out, write_toa);
    } else {
        cudaFuncSetAttribute(shoebox_rir_small,
                             cudaFuncAttributeMaxDynamicSharedMemorySize, small_smem);
        shoebox_rir_small<<<NBATCH, SUBTH, small_smem>>>(in, out, write_toa);
    }
}

// round 5
// speedup vs baseline: 2.9890x; 1.7424x over previous
#include <cuda_runtime.h>

// ShoeboxToRIR: image-source RIR, B=256 rooms, 1561 images (|g|_1 <= 10),
// 81-tap windowed sinc per image scattered into rir[8000], plus toa[256].
//
// Round 5 design:
//  - compile-time constexpr table slot -> (gx,gy,gz,E)  (no decode kernel)
//  - 256 CTAs x 768 threads: 6 sub-blocks of 128, each with a PRIVATE padded
//    smem RIR copy (8128 floats), each processing 1/6 of the images (261).
//  - branchless inner loop: invalid lanes write to a per-thread dummy slot;
//    tap j==80 proven always-zero; (-1)^j sign folded into per-image q and
//    a final (-1)^p in phase 3; frac clamp removes the x==0 special case.

#define NIMG    1561
#define NBATCH  256
#define RIRLEN  8000
#define RIRPAD  8128     // 8000 data + 128 dummy slots
#define PADK    40

struct GTab { int v[NIMG]; };

static constexpr int cabs_(int x) { return x < 0 ? -x : x; }

static constexpr GTab make_gtab() {
    GTab g{};
    int s = 0;
    for (int x = -10; x <= 10; ++x)
        for (int y = -10; y <= 10; ++y)
            for (int z = -10; z <= 10; ++z) {
                int E = cabs_(x) + cabs_(y) + cabs_(z);
                if (E <= 10)
                    g.v[s++] = (x + 10) | ((y + 10) << 5) | ((z + 10) << 10) | (E << 15);
            }
    return g;
}

__device__ constexpr GTab G = make_gtab();

template<int NS>
__global__ __launch_bounds__(NS * 128, 1)
void rir_kernel(const float* __restrict__ in, float* __restrict__ out, int write_toa)
{
    extern __shared__ float smem[];
    float*  rir_s  = smem;                            // NS * RIRPAD floats
    float4* params = (float4*)(smem + NS * RIRPAD);   // NIMG float4

    const int NTH = NS * 128;
    const int b   = blockIdx.x;
    const int tid = threadIdx.x;
    const int sub = tid >> 7;
    const int t   = tid & 127;

    // zero private RIR copies (incl. dummy slots)
    for (int p = tid; p < NS * RIRPAD; p += NTH) rir_s[p] = 0.0f;

    // ---- phase 1: per-image parameters ----
    const float* ip = in + b * 10;
    const float rx = ip[0], ry = ip[1], rz = ip[2];
    const float mx = ip[3] * rx, my = ip[4] * ry, mz = ip[5] * rz;
    const float sx = ip[6] * rx, sy = ip[7] * ry, sz = ip[8] * rz;
    const float ltr = __log2f(sqrtf(1.0f - ip[9]));
    const float PI_F = 3.14159265358979323846f;

    for (int slot = tid; slot < NIMG; slot += NTH) {
        const int pk = G.v[slot];
        const int gx = (pk & 31) - 10;
        const int gy = ((pk >> 5) & 31) - 10;
        const int gz = ((pk >> 10) & 31) - 10;
        const int E  = pk >> 15;

        const float ix = (gx & 1) ? (rx * (float)(gx + 1) - sx) : (rx * (float)gx + sx);
        const float iy = (gy & 1) ? (ry * (float)(gy + 1) - sy) : (ry * (float)gy + sy);
        const float iz = (gz & 1) ? (rz * (float)(gz + 1) - sz) : (rz * (float)gz + sz);

        const float dx = ix - mx, dy = iy - my, dz = iz - mz;
        const float dist = sqrtf(dx * dx + dy * dy + dz * dz);

        const float amp   = __fdividef(exp2f((float)E * ltr), dist);  // tr^E / dist
        const float delay = dist * (16000.0f / 343.0f);
        const float di    = ceilf(delay);
        float frac = di - delay;                 // 0 or >= ulp(delay) ~ 2.4e-4
        frac = fmaxf(frac, 1e-9f);               // kill the x==0 case exactly
        const int   dii = (int)di;
        const int   a   = dii - PADK;
        const float sgn = (dii & 1) ? -1.0f : 1.0f;       // (-1)^a == (-1)^di
        const float q   = sgn * amp * sinpif(frac) * (1.0f / PI_F);

        params[slot] = make_float4(q, frac, __int_as_float(a), 0.0f);
    }

    if (tid == 0 && write_toa) {
        const float ddx = mx - sx, ddy = my - sy, ddz = mz - sz;
        out[NBATCH * RIRLEN + b] =
            40.0f + sqrtf(ddx * ddx + ddy * ddy + ddz * ddz) * (16000.0f / 343.0f);
    }
    __syncthreads();

    // ---- phase 2: branchless accumulation, thread t owns samples == t (mod 128) ----
    const int CH = (NIMG + NS - 1) / NS;
    const int i0 = sub * CH;
    const int i1 = (i0 + CH < NIMG) ? (i0 + CH) : NIMG;
    float* myrir = rir_s + sub * RIRPAD;
    const float PI_OV_40 = 0.07853981633974483f;
    const int dummy = RIRLEN + t;                // per-thread scratch, conflict-free

    #pragma unroll 4
    for (int i = i0; i < i1; ++i) {
        const float4 p = params[i];              // LDS.128 broadcast
        const int a   = __float_as_int(p.z);
        const int j   = (t - a) & 127;           // owned tap index
        const int pos = a + j;                   // == t (mod 128)
        const bool valid = (j < 80) & ((unsigned)pos < (unsigned)RIRLEN);
        const float x  = (float)(j - PADK) + p.y;            // never 0 when valid
        const float hv = 0.5f + 0.5f * __cosf(x * PI_OV_40); // hann
        const float v  = __fdividef(p.x, x) * hv;            // q/x * hann
        const int ps = valid ? pos : dummy;
        myrir[ps] += v;                          // LDS+FADD+STS, no conflicts
    }
    __syncthreads();

    // ---- phase 3: reduce copies, apply (-1)^p, write (coalesced) ----
    float* orow = out + (size_t)b * RIRLEN;
    for (int p = tid; p < RIRLEN; p += NTH) {
        float v = 0.0f;
        #pragma unroll
        for (int s = 0; s < NS; ++s) v += rir_s[s * RIRPAD + p];
        orow[p] = (p & 1) ? -v : v;
    }
}

extern "C" void kernel_launch(void* const* d_in, const int* in_sizes, int n_in,
                              void* d_out, int out_size)
{
    const float* in  = (const float*)d_in[0];
    float*       out = (float*)d_out;
    const int write_toa = (out_size >= NBATCH * RIRLEN + NBATCH) ? 1 : 0;

    const int smem6 = 6 * RIRPAD * 4 + NIMG * 16;   // 220048
    const int smem4 = 4 * RIRPAD * 4 + NIMG * 16;   // 155024
    const int smem1 = 1 * RIRPAD * 4 + NIMG * 16;   //  57488

    if (cudaFuncSetAttribute(rir_kernel<6>,
            cudaFuncAttributeMaxDynamicSharedMemorySize, smem6) == cudaSuccess) {
        rir_kernel<6><<<NBATCH, 6 * 128, smem6>>>(in, out, write_toa);
    } else if (cudaFuncSetAttribute(rir_kernel<4>,
            cudaFuncAttributeMaxDynamicSharedMemorySize, smem4) == cudaSuccess) {
        rir_kernel<4><<<NBATCH, 4 * 128, smem4>>>(in, out, write_toa);
    } else {
        cudaFuncSetAttribute(rir_kernel<1>,
            cudaFuncAttributeMaxDynamicSharedMemorySize, smem1);
        rir_kernel<1><<<NBATCH, 128, smem1>>>(in, out, write_toa);
    }
}

// round 7
// speedup vs baseline: 3.1437x; 1.0518x over previous
#include <cuda_runtime.h>

// ShoeboxToRIR — round 7 (round 6 structure + frac-precision fix).
// grid 512 = (batch 256) x (image-half 2); 384 threads = 3 sub-blocks of 128.
// Each sub-block: private padded smem RIR copy, ~261 images of its half.
// Thread t owns samples == t (mod 128). Byte-space index math, single
// predicate (jb<320), pad-absorbed out-of-range taps. Half 0 -> d_out,
// half 1 -> scratch; combine kernel adds (deterministic, no atomics).
//
// FIX vs round 6: params carry frac at FULL precision (not frac-40, which
// rounded to exactly -40.0f for frac < 1.9e-6 and made x==0 -> inf).
// x = fmaf(jb, 0.25f, -40.0f) + frac  (fmaf part exact: j-40).

#define NIMG    1561
#define NHALF   781          // images in half 0 (half 1 has 780)
#define NBATCH  256
#define RIRLEN  8000
#define NS      3
#define NTH     (NS * 128)
#define COPYLEN 8256         // 48 lower pad + 8000 + 208 upper pad (floats)
#define LOWPAD  48
#define PADK    40

struct GTab { int v[NIMG]; };
static constexpr int cabs_(int x) { return x < 0 ? -x : x; }
static constexpr GTab make_gtab() {
    GTab g{}; int s = 0;
    for (int x = -10; x <= 10; ++x)
        for (int y = -10; y <= 10; ++y)
            for (int z = -10; z <= 10; ++z) {
                int E = cabs_(x) + cabs_(y) + cabs_(z);
                if (E <= 10)
                    g.v[s++] = (x + 10) | ((y + 10) << 5) | ((z + 10) << 10) | (E << 15);
            }
    return g;
}
__device__ constexpr GTab G = make_gtab();

__device__ __align__(16) float g_scratch[NBATCH * RIRLEN];   // half-1 partial RIRs

__global__ __launch_bounds__(NTH, 2)
void rir_half_kernel(const float* __restrict__ in, float* __restrict__ out, int write_toa)
{
    extern __shared__ float smem[];
    float*  rir_s  = smem;                          // NS * COPYLEN
    float4* params = (float4*)(smem + NS * COPYLEN);// up to NHALF float4

    const int bx  = blockIdx.x;
    const int b   = bx & 255;
    const int h   = bx >> 8;            // 0 or 1
    const int tid = threadIdx.x;
    const int sub = tid >> 7;
    const int t   = tid & 127;

    // zero private copies (16B vectorized)
    {
        float4* z = (float4*)rir_s;
        for (int p = tid; p < NS * COPYLEN / 4; p += NTH)
            z[p] = make_float4(0.f, 0.f, 0.f, 0.f);
    }

    // ---- phase 1: params for this half's images ----
    const float* ip = in + b * 10;
    const float rx = ip[0], ry = ip[1], rz = ip[2];
    const float mx = ip[3] * rx, my = ip[4] * ry, mz = ip[5] * rz;
    const float sx = ip[6] * rx, sy = ip[7] * ry, sz = ip[8] * rz;
    const float ltr = __log2f(sqrtf(1.0f - ip[9]));
    const float PI_F = 3.14159265358979323846f;

    const int s0 = h * NHALF;
    const int nh = (h == 0) ? NHALF : (NIMG - NHALF);

    for (int sl = tid; sl < nh; sl += NTH) {
        const int pk = G.v[s0 + sl];
        const int gx = (pk & 31) - 10;
        const int gy = ((pk >> 5) & 31) - 10;
        const int gz = ((pk >> 10) & 31) - 10;
        const int E  = pk >> 15;

        const float ix = (gx & 1) ? (rx * (float)(gx + 1) - sx) : (rx * (float)gx + sx);
        const float iy = (gy & 1) ? (ry * (float)(gy + 1) - sy) : (ry * (float)gy + sy);
        const float iz = (gz & 1) ? (rz * (float)(gz + 1) - sz) : (rz * (float)gz + sz);

        const float dx = ix - mx, dy = iy - my, dz = iz - mz;
        const float dist = sqrtf(dx * dx + dy * dy + dz * dz);

        const float amp   = __fdividef(exp2f((float)E * ltr), dist);
        const float delay = dist * (16000.0f / 343.0f);
        const float di    = ceilf(delay);
        float frac = fmaxf(di - delay, 1e-9f);       // exact subtraction; clamp kills x==0
        const int dii = (int)di;
        int a = dii - PADK;
        float q = ((dii & 1) ? -amp : amp) * sinpif(frac) * (1.0f / PI_F);
        if (a >= RIRLEN) { a = RIRLEN; q = 0.0f; }   // zero taps land in upper pad

        params[sl] = make_float4(q, frac, __int_as_float(a * 4), 0.0f);
    }

    if (tid == 0 && h == 0 && write_toa) {
        const float ddx = mx - sx, ddy = my - sy, ddz = mz - sz;
        out[NBATCH * RIRLEN + b] =
            40.0f + sqrtf(ddx * ddx + ddy * ddy + ddz * ddz) * (16000.0f / 343.0f);
    }
    __syncthreads();

    // ---- phase 2: single-predicate byte-space accumulation ----
    const int CH = (NHALF + NS - 1) / NS;            // 261
    const int i0 = sub * CH;
    const int i1 = (i0 + CH < nh) ? (i0 + CH) : nh;
    char* myrir_b = (char*)(rir_s + sub * COPYLEN + LOWPAD);
    const int t4 = t * 4;
    const float PI40 = 0.07853981633974483f;

    #pragma unroll 4
    for (int i = i0; i < i1; ++i) {
        const float4 p = params[i];                   // broadcast LDS.128
        const int a4 = __float_as_int(p.z);
        const int jb = (t4 - a4) & 508;               // 4*j, j = (t-a) mod 128
        const float x  = fmaf((float)jb, 0.25f, -40.0f) + p.y;  // (j-40)+frac, exact, never 0
        const float hv = 0.5f + 0.5f * __cosf(x * PI40);        // hann
        const float v  = __fdividef(p.x, x) * hv;               // q/x * hann
        if (jb < 320) {                               // j < 80 (predicated RMW)
            float* ap = (float*)(myrir_b + a4 + jb);
            *ap += v;
        }
    }
    __syncthreads();

    // ---- phase 3: reduce NS copies, apply (-1)^pos, write ----
    float* orow = (h == 0 ? out : g_scratch) + (size_t)b * RIRLEN;
    for (int p = tid; p < RIRLEN; p += NTH) {
        float v = 0.0f;
        #pragma unroll
        for (int s = 0; s < NS; ++s) v += rir_s[s * COPYLEN + LOWPAD + p];
        orow[p] = (p & 1) ? -v : v;
    }
}

__global__ __launch_bounds__(256)
void combine_kernel(float* __restrict__ out)
{
    const int b = blockIdx.x;
    float4*       o = (float4*)(out + (size_t)b * RIRLEN);
    const float4* s = (const float4*)(g_scratch + (size_t)b * RIRLEN);
    for (int i = threadIdx.x; i < RIRLEN / 4; i += 256) {
        float4 a = o[i], c = s[i];
        a.x += c.x; a.y += c.y; a.z += c.z; a.w += c.w;
        o[i] = a;
    }
}

extern "C" void kernel_launch(void* const* d_in, const int* in_sizes, int n_in,
                              void* d_out, int out_size)
{
    const float* in  = (const float*)d_in[0];
    float*       out = (float*)d_out;
    const int write_toa = (out_size >= NBATCH * RIRLEN + NBATCH) ? 1 : 0;

    const int smem_bytes = NS * COPYLEN * 4 + NHALF * 16;   // 99072 + 12496 = 111568
    cudaFuncSetAttribute(rir_half_kernel,
                         cudaFuncAttributeMaxDynamicSharedMemorySize, smem_bytes);

    rir_half_kernel<<<2 * NBATCH, NTH, smem_bytes>>>(in, out, write_toa);
    combine_kernel<<<NBATCH, 256>>>(out);
}